// round 7
// baseline (speedup 1.0000x reference)
#include <cuda_runtime.h>
#include <cuda_bf16.h>
#include <math.h>

// Problem constants (fixed by dataset: B=4, H=W=320)
#define H_DIM 320
#define W_DIM 320
#define B_DIM 4
#define TILE 32                 // tile is 32x32 pixels
#define BLK_Y 16                // 32x16 threads, 2 pixels per thread
#define HALO 8
#define SROWS (TILE + 2 * HALO) // 48 rows incl. halo
#define NBLK_X (W_DIM / TILE)   // 10
#define NBLK_Y (H_DIM / TILE)   // 10
#define NBLOCKS (NBLK_X * NBLK_Y * B_DIM) // 400

__device__ float g_blockSums[NBLOCKS];
__device__ unsigned int g_arrived = 0;

// Per-byte dy^2 addends for the packed vertical pass.
// c_addc[phase][i], byte j corresponds to dy = 4*i + j - phase - 8;
// value = dy*dy if |dy| <= 8 else 255 (mask). phase = ty & 3.
__constant__ unsigned int c_addc[4][5] = {
    {0x19243140u, 0x01040910u, 0x09040100u, 0x31241910u, 0xFFFFFF40u},
    {0x243140FFu, 0x04091019u, 0x04010001u, 0x24191009u, 0xFFFF4031u},
    {0x3140FFFFu, 0x09101924u, 0x01000104u, 0x19100904u, 0xFF403124u},
    {0x40FFFFFFu, 0x10192431u, 0x00010409u, 0x10090401u, 0x40312419u},
};

// Exact global fallback. Entered with an INF bound when the 17x17 window has
// no usable seed (window values <= 81 are provably the exact global min,
// since any seed outside the window has d^2 >= 81).
__device__ __noinline__ int global_ring_search(const int* __restrict__ targets,
                                               int planeOff, int gh, int gw, int best)
{
    for (int r = HALO + 1; r < H_DIM + W_DIM; ++r) {
        if (r * r >= best) break;
        const int rr = r * r;
        const int yT = gh - r, yB = gh + r;
        for (int dx = -r; dx <= r; ++dx) {
            int d2 = rr + dx * dx;
            if (d2 >= best) continue;
            int x = gw + dx;
            if (x < 0 || x >= W_DIM) continue;
            if (yT >= 0 && targets[planeOff + yT * W_DIM + x] > 0) best = d2;
            if (yB < H_DIM && d2 < best && targets[planeOff + yB * W_DIM + x] > 0) best = d2;
        }
        const int xL = gw - r, xR = gw + r;
        for (int dy = -r + 1; dy <= r - 1; ++dy) {
            int d2 = rr + dy * dy;
            if (d2 >= best) continue;
            int y = gh + dy;
            if (y < 0 || y >= H_DIM) continue;
            if (xL >= 0 && targets[planeOff + y * W_DIM + xL] > 0) best = d2;
            if (xR < W_DIM && d2 < best && targets[planeOff + y * W_DIM + xR] > 0) best = d2;
        }
    }
    return best;
}

__global__ __launch_bounds__(512)
void edt_loss_kernel(const float* __restrict__ logits,
                     const int* __restrict__ targets,
                     float* __restrict__ out)
{
    // s_pack[g][tx]: byte j holds nearest-dx^2 (<=64, or 127 = row empty)
    // for mask row 4g+j at column tx. 1.5 KB, conflict-free word access.
    __shared__ unsigned int s_pack[12][32];
    __shared__ float s_warp[16];
    __shared__ int s_isLast;

    const int tx   = threadIdx.x;                 // 0..31 (== lane)
    const int ty   = threadIdx.y;                 // 0..15 (== warp)
    const int tid  = ty * 32 + tx;
    const int warp = ty;
    const int lane = tx;
    const int h0 = blockIdx.y * TILE;
    const int w0 = blockIdx.x * TILE;
    const int planeOff = blockIdx.z * (H_DIM * W_DIM);
    const int gw = w0 + tx;

    // ---- Unconditional clamped loads: one memory round, full MLP ----
    float x0 = logits[planeOff + (h0 + ty) * W_DIM + gw];
    float x1 = logits[planeOff + (h0 + ty + 16) * W_DIM + gw];

    const int* rowBase = targets + planeOff;
    int av[3], bv[3];
    bool avOK[3], bvOK[3];
    #pragma unroll
    for (int k = 0; k < 3; ++k) {
        int grow = h0 - HALO + warp + k * 16;     // 0..47 -> global row
        int growC = min(max(grow, 0), H_DIM - 1);
        bool rv = (grow >= 0) && (grow < H_DIM);
        int c0 = w0 - HALO + lane;
        int c0C = min(max(c0, 0), W_DIM - 1);
        avOK[k] = rv && (c0 >= 0) && (c0 < W_DIM);
        av[k] = __ldg(rowBase + growC * W_DIM + c0C);
        int c1 = min(w0 + 24 + lane, W_DIM - 1);
        bvOK[k] = rv && (lane < 16) && (w0 + 24 + lane < W_DIM);
        bv[k] = __ldg(rowBase + growC * W_DIM + c1);
    }

    // ---- Ballot-assemble 48-bit row masks + horizontal nearest-dx pass ----
    #pragma unroll
    for (int k = 0; k < 3; ++k) {
        unsigned int lo = __ballot_sync(0xffffffffu, avOK[k] && (av[k] > 0));
        unsigned int hi = __ballot_sync(0xffffffffu, bvOK[k] && (bv[k] > 0));
        unsigned long long m =
            (unsigned long long)lo | ((unsigned long long)(hi & 0xFFFFu) << 32);
        unsigned int win = (unsigned int)(m >> tx) & 0x1FFFFu;
        unsigned int r = win >> 8;                 // dx = 0..8
        unsigned int l = win & 0x1FFu;             // dx = -8..0
        int dxr = r ? (__ffs(r) - 1) : 127;
        int dxl = l ? (__clz(l) - 23) : 127;
        int dx = min(dxr, dxl);
        int row = warp + k * 16;
        ((unsigned char*)&s_pack[row >> 2][tx])[row & 3] =
            (unsigned char)min(dx * dx, 127);
    }
    __syncthreads();

    // ---- SIMD-byte vertical min-plus: 5 LDS + 5 vaddus4 + 4 vminu4 / pixel ----
    const int phase = ty & 3;
    const int g0 = ty >> 2;
    unsigned int addc[5];
    #pragma unroll
    for (int i = 0; i < 5; ++i) addc[i] = c_addc[phase][i];   // uniform per warp

    float acc = 0.0f;
    #pragma unroll
    for (int half = 0; half < 2; ++half) {
        const int gs = g0 + half * 4;             // pixel row ry = ty + 8 + 16*half
        unsigned int m = 0xFFFFFFFFu;
        #pragma unroll
        for (int i = 0; i < 5; ++i)
            m = __vminu4(m, __vaddus4(s_pack[gs + i][tx], addc[i]));
        m = __vminu4(m, m >> 16);
        m = __vminu4(m, m >> 8);
        int best = (int)(m & 0xFFu);

        if (best > 81) {   // window inconclusive (sentinel-involved); exact fallback
            best = global_ring_search(targets, planeOff, h0 + ty + half * 16, gw,
                                      0x3fffffff);
        }
        float dist = __fsqrt_rn((float)best);
        float x = half ? x1 : x0;
        float p = __fdividef(1.0f, 1.0f + __expf(-x));
        acc += fmaf(p, dist, 1.0f - p);
    }

    // ---- Deterministic block reduction (FP32, fixed order) ----
    #pragma unroll
    for (int off = 16; off > 0; off >>= 1)
        acc += __shfl_down_sync(0xffffffffu, acc, off);
    if (lane == 0) s_warp[warp] = acc;
    __syncthreads();
    if (warp == 0) {
        float v = (lane < 16) ? s_warp[lane] : 0.0f;
        #pragma unroll
        for (int off = 8; off > 0; off >>= 1)
            v += __shfl_down_sync(0xffffffffu, v, off);
        if (lane == 0) {
            int blockIndex = (blockIdx.z * NBLK_Y + blockIdx.y) * NBLK_X + blockIdx.x;
            g_blockSums[blockIndex] = v;
        }
    }

    // ---- Last-arriving block finishes (acq_rel atomic orders sums) ----
    if (tid == 0) {
        unsigned int t;
        asm volatile("atom.acq_rel.gpu.global.add.u32 %0, [%1], %2;"
                     : "=r"(t) : "l"(&g_arrived), "r"(1u) : "memory");
        s_isLast = (t == (unsigned int)(NBLOCKS - 1)) ? 1 : 0;
    }
    __syncthreads();
    if (s_isLast) {
        float v = 0.0f;
        for (int i = tid; i < NBLOCKS; i += 512) v += __ldcg(&g_blockSums[i]);
        #pragma unroll
        for (int off = 16; off > 0; off >>= 1)
            v += __shfl_down_sync(0xffffffffu, v, off);
        if (lane == 0) s_warp[warp] = v;
        __syncthreads();
        if (warp == 0) {
            float t = (lane < 16) ? s_warp[lane] : 0.0f;
            #pragma unroll
            for (int off = 8; off > 0; off >>= 1)
                t += __shfl_down_sync(0xffffffffu, t, off);
            if (lane == 0) {
                out[0] = t / (float)(B_DIM * H_DIM * W_DIM);
                g_arrived = 0;   // reset for next graph replay
            }
        }
    }
}

extern "C" void kernel_launch(void* const* d_in, const int* in_sizes, int n_in,
                              void* d_out, int out_size)
{
    const float* logits  = (const float*)d_in[0];
    const int*   targets = (const int*)d_in[1];
    float* out = (float*)d_out;

    dim3 block(32, BLK_Y, 1);
    dim3 grid(NBLK_X, NBLK_Y, B_DIM);
    edt_loss_kernel<<<grid, block>>>(logits, targets, out);
}

// round 8
// speedup vs baseline: 1.2435x; 1.2435x over previous
#include <cuda_runtime.h>
#include <cuda_bf16.h>
#include <math.h>

// Problem constants (fixed by dataset: B=4, H=W=320)
#define H_DIM 320
#define W_DIM 320
#define B_DIM 4
#define TILE 32                 // tile is 32x32 pixels
#define BLK_Y 16                // 32x16 threads, 2 pixels per thread
#define HALO 8
#define SROWS (TILE + 2 * HALO) // 48 rows incl. halo
#define NBLK_X (W_DIM / TILE)   // 10
#define NBLK_Y (H_DIM / TILE)   // 10
#define NBLOCKS (NBLK_X * NBLK_Y * B_DIM) // 400

__device__ float g_blockSums[NBLOCKS];
__device__ unsigned int g_arrived = 0;

// Exact global fallback (required for exactness when no seed within the
// Chebyshev-8 window beats the outside: outside => d^2 >= 81).
__device__ __noinline__ int global_ring_search(const int* __restrict__ targets,
                                               int planeOff, int gh, int gw, int best)
{
    for (int r = HALO + 1; r < H_DIM + W_DIM; ++r) {
        if (r * r >= best) break;
        const int rr = r * r;
        const int yT = gh - r, yB = gh + r;
        for (int dx = -r; dx <= r; ++dx) {
            int d2 = rr + dx * dx;
            if (d2 >= best) continue;
            int x = gw + dx;
            if (x < 0 || x >= W_DIM) continue;
            if (yT >= 0 && targets[planeOff + yT * W_DIM + x] > 0) best = d2;
            if (yB < H_DIM && d2 < best && targets[planeOff + yB * W_DIM + x] > 0) best = d2;
        }
        const int xL = gw - r, xR = gw + r;
        for (int dy = -r + 1; dy <= r - 1; ++dy) {
            int d2 = rr + dy * dy;
            if (d2 >= best) continue;
            int y = gh + dy;
            if (y < 0 || y >= H_DIM) continue;
            if (xL >= 0 && targets[planeOff + y * W_DIM + xL] > 0) best = d2;
            if (xR < W_DIM && d2 < best && targets[planeOff + y * W_DIM + xR] > 0) best = d2;
        }
    }
    return best;
}

// Fused vertical min-plus for two vertically adjacent pixels (centers r, r+1).
// Rolling 2-register window: 18 LDS + ~50 ALU for BOTH pixels.
__device__ __forceinline__ void vertical_min_pair(const unsigned int* __restrict__ col,
                                                  int r, int& best0, int& best1)
{
    const unsigned int* c = col + r * 32;       // row (r+k) at c[32*k]
    int prev_up = (int)c[0];                    // v[r - (d-1)] after step d-1
    int prev_dn = (int)c[32];                   // v[r + d]     after step d-1
    int b0 = prev_up, b1 = prev_dn;
    #pragma unroll
    for (int d = 1; d <= 8; ++d) {
        int nu = (int)c[-d * 32];               // v[r - d]
        int nd = (int)c[(d + 1) * 32];          // v[r + 1 + d]
        b0 = min(b0, min(nu, prev_dn) + d * d); // pixel0 rows r-d, r+d
        b1 = min(b1, min(prev_up, nd) + d * d); // pixel1 rows r+1-d, r+1+d
        prev_up = nu;
        prev_dn = nd;
    }
    best0 = b0;
    best1 = b1;
}

__global__ __launch_bounds__(512, 3)
void edt_loss_kernel(const float* __restrict__ logits,
                     const int* __restrict__ targets,
                     float* __restrict__ out)
{
    __shared__ unsigned int s_dxsq[SROWS][32];    // nearest dx^2 per (row, col); 6 KB
    __shared__ float s_warp[16];
    __shared__ int s_isLast;

    const int tx   = threadIdx.x;                 // 0..31 (== lane)
    const int ty   = threadIdx.y;                 // 0..15 (== warp)
    const int tid  = ty * 32 + tx;
    const int warp = ty;
    const int lane = tx;
    const int h0 = blockIdx.y * TILE;
    const int w0 = blockIdx.x * TILE;
    const int planeOff = blockIdx.z * (H_DIM * W_DIM);
    const int gw = w0 + tx;

    // ---- Hoist ALL global loads: one memory round, full MLP ----
    // Warp ty owns pixel rows 2ty and 2ty+1.
    float x0 = logits[planeOff + (h0 + 2 * ty) * W_DIM + gw];
    float x1 = logits[planeOff + (h0 + 2 * ty + 1) * W_DIM + gw];

    const int* rowBase = targets + planeOff;
    int av[3] = {0, 0, 0};
    int bv[3] = {0, 0, 0};
    #pragma unroll
    for (int k = 0; k < 3; ++k) {
        int grow = h0 - HALO + warp + k * 16;     // 0..47 -> global row
        bool rv = (grow >= 0) && (grow < H_DIM);
        int c0 = w0 - HALO + lane;
        if (rv && c0 >= 0 && c0 < W_DIM) av[k] = __ldg(rowBase + grow * W_DIM + c0);
        int c1 = w0 + 24 + lane;
        if (rv && lane < 16 && c1 < W_DIM)  bv[k] = __ldg(rowBase + grow * W_DIM + c1);
    }

    // ---- Sigmoids early: overlap with ballot/horizontal phase ----
    float p0 = __fdividef(1.0f, 1.0f + __expf(-x0));
    float p1 = __fdividef(1.0f, 1.0f + __expf(-x1));

    // ---- Ballot-assemble 48-bit row masks + horizontal nearest-dx pass ----
    #pragma unroll
    for (int k = 0; k < 3; ++k) {
        unsigned int lo = __ballot_sync(0xffffffffu, av[k] > 0);
        unsigned int hi = __ballot_sync(0xffffffffu, bv[k] > 0); // lanes>=16 give 0
        unsigned long long m =
            (unsigned long long)lo | ((unsigned long long)(hi & 0xFFFFu) << 32);
        unsigned int win = (unsigned int)(m >> tx) & 0x1FFFFu;
        unsigned int r = win >> 8;                 // dx = 0..8
        unsigned int l = win & 0x1FFu;             // dx = -8..0
        int dxr = r ? (__ffs(r) - 1) : 127;
        int dxl = l ? (__clz(l) - 23) : 127;
        int dx = min(dxr, dxl);
        s_dxsq[warp + k * 16][tx] = (unsigned int)min(dx * dx, 127);
    }
    __syncthreads();

    // ---- Fused vertical pass for the pixel pair + loss (FP32) ----
    const unsigned int* col = &s_dxsq[0][tx];
    int best0, best1;
    vertical_min_pair(col, 2 * ty + HALO, best0, best1);
    if (best0 > 81)
        best0 = global_ring_search(targets, planeOff, h0 + 2 * ty, gw, 0x3fffffff);
    if (best1 > 81)
        best1 = global_ring_search(targets, planeOff, h0 + 2 * ty + 1, gw, 0x3fffffff);

    float acc = fmaf(p0, __fsqrt_rn((float)best0), 1.0f - p0)
              + fmaf(p1, __fsqrt_rn((float)best1), 1.0f - p1);

    // ---- Deterministic block reduction (FP32, fixed order) ----
    #pragma unroll
    for (int off = 16; off > 0; off >>= 1)
        acc += __shfl_down_sync(0xffffffffu, acc, off);
    if (lane == 0) s_warp[warp] = acc;
    __syncthreads();
    if (warp == 0) {
        float v = (lane < 16) ? s_warp[lane] : 0.0f;
        #pragma unroll
        for (int off = 8; off > 0; off >>= 1)
            v += __shfl_down_sync(0xffffffffu, v, off);
        if (lane == 0) {
            int blockIndex = (blockIdx.z * NBLK_Y + blockIdx.y) * NBLK_X + blockIdx.x;
            g_blockSums[blockIndex] = v;
        }
    }

    // ---- Last-arriving block finishes (acq_rel atomic orders sums) ----
    if (tid == 0) {
        unsigned int t;
        asm volatile("atom.acq_rel.gpu.global.add.u32 %0, [%1], %2;"
                     : "=r"(t) : "l"(&g_arrived), "r"(1u) : "memory");
        s_isLast = (t == (unsigned int)(NBLOCKS - 1)) ? 1 : 0;
    }
    __syncthreads();
    if (s_isLast) {
        float v = 0.0f;
        for (int i = tid; i < NBLOCKS; i += 512) v += __ldcg(&g_blockSums[i]);
        #pragma unroll
        for (int off = 16; off > 0; off >>= 1)
            v += __shfl_down_sync(0xffffffffu, v, off);
        if (lane == 0) s_warp[warp] = v;
        __syncthreads();
        if (warp == 0) {
            float t = (lane < 16) ? s_warp[lane] : 0.0f;
            #pragma unroll
            for (int off = 8; off > 0; off >>= 1)
                t += __shfl_down_sync(0xffffffffu, t, off);
            if (lane == 0) {
                out[0] = t / (float)(B_DIM * H_DIM * W_DIM);
                g_arrived = 0;   // reset for next graph replay
            }
        }
    }
}

extern "C" void kernel_launch(void* const* d_in, const int* in_sizes, int n_in,
                              void* d_out, int out_size)
{
    const float* logits  = (const float*)d_in[0];
    const int*   targets = (const int*)d_in[1];
    float* out = (float*)d_out;

    dim3 block(32, BLK_Y, 1);
    dim3 grid(NBLK_X, NBLK_Y, B_DIM);
    edt_loss_kernel<<<grid, block>>>(logits, targets, out);
}